// round 7
// baseline (speedup 1.0000x reference)
#include <cuda_runtime.h>
#include <cuda_bf16.h>

// ---------------------------------------------------------------------------
// BarbershopTransformer: 6-layer GPT forward, B=32 T=256 C=384 H=6 D=64 V=32000
// Round 6: fix (M,N,K) argument order at W1 / W2 / LM-head call sites
// (was passing (M,K,N); clamps masked it as rel_err instead of a crash).
// ---------------------------------------------------------------------------

#define NL    6
#define C     384
#define HN    6
#define HD    64
#define TT    256
#define BB    32
#define M_TOK (BB*TT)          // 8192
#define FF    (4*C)            // 1536
#define V     32000

__device__ float g_x  [M_TOK*C];
__device__ float g_h  [M_TOK*C];
__device__ float g_q  [M_TOK*C];
__device__ float g_k  [M_TOK*C];
__device__ float g_v  [M_TOK*C];
__device__ float g_att[M_TOK*C];
__device__ float g_mlp[M_TOK*FF];

#define WBUF_TOTAL 35349248
__device__ float g_wbuf[WBUF_TOTAL];
__device__ int   g_in_bf16;
__device__ int   g_out_bf16;

__device__ __forceinline__ float* buf_sel(int s) {
    switch (s) {
        case 0: return g_x;
        case 1: return g_h;
        case 2: return g_q;
        case 3: return g_k;
        case 4: return g_v;
        case 5: return g_att;
        default: return g_mlp;   // 6
    }
}
__device__ __forceinline__ long long buf_cap(int s) {
    return (s == 6) ? (long long)M_TOK * FF : (long long)M_TOK * C;
}

// ---------------------------------------------------------------------------
__global__ void flags_kernel(const void* buf, int in_mode, int out_mode) {
    __shared__ int sh;
    int tid = threadIdx.x;
    if (tid == 0) sh = 0;
    __syncthreads();
    if (in_mode < 0) {
        const __nv_bfloat16* s = (const __nv_bfloat16*)buf;
        int cnt = 0;
        for (int i = tid; i < 4096; i += 256) {
            float f = __bfloat162float(s[i]);
            if (!isfinite(f) || fabsf(f) > 8.0f) cnt++;
        }
        atomicAdd(&sh, cnt);
    }
    __syncthreads();
    if (tid == 0) {
        int in_bf16 = (in_mode < 0) ? ((sh > 64) ? 0 : 1) : in_mode;
        g_in_bf16  = in_bf16;
        g_out_bf16 = (out_mode < 0) ? in_bf16 : out_mode;
    }
}

__global__ void convert_kernel(const void* src, long long off, int n) {
    int i = blockIdx.x * blockDim.x + threadIdx.x;
    if (i >= n) return;
    float vv;
    if (g_in_bf16) vv = __bfloat162float(((const __nv_bfloat16*)src)[i]);
    else           vv = ((const float*)src)[i];
    long long o = off + i;
    if (o >= 0 && o < WBUF_TOTAL) g_wbuf[o] = vv;
}

// ---------------------------------------------------------------------------
__global__ void embed_kernel(const int* __restrict__ idx,
                             long long tokOff, long long posOff) {
    int m = blockIdx.x;
    int c = threadIdx.x;
    int t = m & (TT - 1);
    int tk = idx[m];
    if ((unsigned)tk >= (unsigned)V) tk = 0;
    const float* tok = g_wbuf + tokOff;
    const float* pos = g_wbuf + posOff;
    g_x[m * C + c] = tok[tk * C + c] + pos[t * C + c];
}

// ---------------------------------------------------------------------------
__global__ void ln_kernel(int inSel, long long gOff, long long bOff, int outSel) {
    __shared__ float red[4];
    __shared__ float stat[2];
    const float* x = buf_sel(inSel);
    float* out     = buf_sel(outSel);
    const float* g = g_wbuf + gOff;
    const float* b = g_wbuf + bOff;
    int row = blockIdx.x, tid = threadIdx.x;
    const float* xr = x + (size_t)row * C;
    float v0 = xr[tid], v1 = xr[tid + 128], v2 = xr[tid + 256];
    float s = v0 + v1 + v2;
    #pragma unroll
    for (int o = 16; o; o >>= 1) s += __shfl_xor_sync(0xffffffffu, s, o);
    if ((tid & 31) == 0) red[tid >> 5] = s;
    __syncthreads();
    if (tid == 0) stat[0] = (red[0] + red[1] + red[2] + red[3]) * (1.0f / C);
    __syncthreads();
    float m = stat[0];
    float d0 = v0 - m, d1 = v1 - m, d2 = v2 - m;
    float q = d0 * d0 + d1 * d1 + d2 * d2;
    #pragma unroll
    for (int o = 16; o; o >>= 1) q += __shfl_xor_sync(0xffffffffu, q, o);
    if ((tid & 31) == 0) red[tid >> 5] = q;
    __syncthreads();
    if (tid == 0)
        stat[1] = rsqrtf((red[0] + red[1] + red[2] + red[3]) * (1.0f / C) + 1e-5f);
    __syncthreads();
    float r = stat[1];
    float* o = out + (size_t)row * C;
    o[tid]       = d0 * r * g[tid]       + b[tid];
    o[tid + 128] = d1 * r * g[tid + 128] + b[tid + 128];
    o[tid + 256] = d2 * r * g[tid + 256] + b[tid + 256];
}

// ---------------------------------------------------------------------------
// SGEMM 128x128x8, 256 thr, 8x8/thread. C[M,N] = A[M,K] @ B[K,N].
template<bool BIAS, bool RELU, bool RES, bool DYNOUT>
__global__ void __launch_bounds__(256)
gemm_kernel(int aSel, long long bOff, long long biasOff,
            int outSel, void* dOutPtr,
            int M, int N, int K, int Mlim) {
    __shared__ float As[8][128];
    __shared__ float Bs[8][128];
    const float* A  = buf_sel(aSel);
    const float* B  = g_wbuf + bOff;
    const float* bi = g_wbuf + biasOff;
    long long aCap = buf_cap(aSel);
    long long bCap = (long long)WBUF_TOTAL - bOff;

    int tid = threadIdx.x;
    int bm = blockIdx.y * 128, bn = blockIdx.x * 128;
    int tx = tid & 15, ty = tid >> 4;

    int arow = tid >> 1;
    int acol = (tid & 1) * 4;
    int brow = tid >> 5;
    int bcol = (tid & 31) * 4;

    float acc[8][8];
    #pragma unroll
    for (int i = 0; i < 8; i++)
        #pragma unroll
        for (int j = 0; j < 8; j++) acc[i][j] = 0.f;

    for (int k0 = 0; k0 < K; k0 += 8) {
        long long aIdx = (long long)(bm + arow) * K + k0 + acol;
        long long bIdx = (long long)(k0 + brow) * N + bn + bcol;
        if (aIdx > aCap - 4) aIdx = aCap - 4;
        if (bIdx > bCap - 4) bIdx = bCap - 4;
        float4 a  = *(const float4*)(A + aIdx);
        float4 bv = *(const float4*)(B + bIdx);
        As[acol + 0][arow] = a.x;
        As[acol + 1][arow] = a.y;
        As[acol + 2][arow] = a.z;
        As[acol + 3][arow] = a.w;
        *(float4*)(&Bs[brow][bcol]) = bv;
        __syncthreads();
        #pragma unroll
        for (int k = 0; k < 8; k++) {
            float af[8], bf[8];
            *(float4*)(af)     = *(const float4*)(&As[k][ty * 8]);
            *(float4*)(af + 4) = *(const float4*)(&As[k][ty * 8 + 4]);
            *(float4*)(bf)     = *(const float4*)(&Bs[k][tx * 8]);
            *(float4*)(bf + 4) = *(const float4*)(&Bs[k][tx * 8 + 4]);
            #pragma unroll
            for (int i = 0; i < 8; i++)
                #pragma unroll
                for (int j = 0; j < 8; j++)
                    acc[i][j] = fmaf(af[i], bf[j], acc[i][j]);
        }
        __syncthreads();
    }

    float bvals[8];
    if (BIAS) {
        #pragma unroll
        for (int j = 0; j < 8; j++) {
            int bidx = bn + tx * 8 + j;
            if ((long long)bidx >= bCap) bidx = 0;
            bvals[j] = bi[bidx];
        }
    }
    bool store_bf16 = DYNOUT ? (g_out_bf16 != 0) : false;
    float* outBuf = DYNOUT ? nullptr : buf_sel(outSel);
    long long oCap = DYNOUT ? ((long long)M_TOK * V) : buf_cap(outSel);

    #pragma unroll
    for (int i = 0; i < 8; i++) {
        int row = bm + ty * 8 + i;
        if (row >= Mlim) continue;
        float out[8];
        #pragma unroll
        for (int j = 0; j < 8; j++) {
            float vv = acc[i][j];
            if (BIAS) vv += bvals[j];
            if (RELU) vv = fmaxf(vv, 0.f);
            out[j] = vv;
        }
        long long base = (long long)row * N + bn + tx * 8;
        if (base > oCap - 8) base = oCap - 8;
        if (RES) {
            long long rbase = base;
            if (rbase > (long long)M_TOK * C - 8) rbase = (long long)M_TOK * C - 8;
            float4 r0 = *(const float4*)(g_x + rbase);
            float4 r1 = *(const float4*)(g_x + rbase + 4);
            out[0] += r0.x; out[1] += r0.y; out[2] += r0.z; out[3] += r0.w;
            out[4] += r1.x; out[5] += r1.y; out[6] += r1.z; out[7] += r1.w;
        }
        if (DYNOUT) {
            if (store_bf16) {
                __nv_bfloat162 pk[4];
                #pragma unroll
                for (int j = 0; j < 4; j++)
                    pk[j] = __floats2bfloat162_rn(out[2 * j], out[2 * j + 1]);
                *(uint4*)((__nv_bfloat16*)dOutPtr + base) = *(uint4*)pk;
            } else {
                float* Cf = (float*)dOutPtr;
                *(float4*)(Cf + base)     = *(float4*)(out);
                *(float4*)(Cf + base + 4) = *(float4*)(out + 4);
            }
        } else {
            *(float4*)(outBuf + base)     = *(float4*)(out);
            *(float4*)(outBuf + base + 4) = *(float4*)(out + 4);
        }
    }
}

// ---------------------------------------------------------------------------
__global__ void __launch_bounds__(256)
attn_kernel() {
    __shared__ float sq[8][64];
    __shared__ float sw[8][256];
    int bh = blockIdx.x;
    int b = bh / HN, h = bh % HN;
    int tid = threadIdx.x, warp = tid >> 5, lane = tid & 31;
    const float scale = rsqrtf((float)C);
    const long long capQ = (long long)M_TOK * C - 64;

    for (int t = warp; t < TT; t += 8) {
        int len = t + 1;
        long long qbase = (long long)(b * TT + t) * C + h * HD;
        if (qbase > capQ) qbase = capQ;
        sq[warp][lane]      = g_q[qbase + lane];
        sq[warp][lane + 32] = g_q[qbase + lane + 32];
        __syncwarp();

        float local[8];
        float mx = -1e30f;
        #pragma unroll
        for (int i = 0; i < 8; i++) {
            int s = lane + i * 32;
            float acc = 0.f;
            if (s < len) {
                long long kbase = (long long)(b * TT + s) * C + h * HD;
                if (kbase > capQ) kbase = capQ;
                const float* krow = g_k + kbase;
                #pragma unroll
                for (int d = 0; d < 64; d++) acc = fmaf(sq[warp][d], krow[d], acc);
                acc *= scale;
                mx = fmaxf(mx, acc);
            }
            local[i] = acc;
        }
        #pragma unroll
        for (int off = 16; off; off >>= 1)
            mx = fmaxf(mx, __shfl_xor_sync(0xffffffffu, mx, off));
        float sum = 0.f;
        #pragma unroll
        for (int i = 0; i < 8; i++) {
            int s = lane + i * 32;
            if (s < len) {
                float e = __expf(local[i] - mx);
                local[i] = e;
                sum += e;
            }
        }
        #pragma unroll
        for (int off = 16; off; off >>= 1)
            sum += __shfl_xor_sync(0xffffffffu, sum, off);
        float inv = 1.f / sum;
        #pragma unroll
        for (int i = 0; i < 8; i++) {
            int s = lane + i * 32;
            if (s < len) sw[warp][s] = local[i] * inv;
        }
        __syncwarp();
        float acc0 = 0.f, acc1 = 0.f;
        for (int s = 0; s < len; s++) {
            float w = sw[warp][s];
            long long vbase = (long long)(b * TT + s) * C + h * HD;
            if (vbase > capQ) vbase = capQ;
            acc0 = fmaf(w, g_v[vbase + lane],      acc0);
            acc1 = fmaf(w, g_v[vbase + lane + 32], acc1);
        }
        g_att[qbase + lane]      = acc0;
        g_att[qbase + lane + 32] = acc1;
    }
}

// ---------------------------------------------------------------------------
static const int SIG_E[20] = {
    8192, 12288000, 98304, 2304, 2304, 884736, 884736, 884736, 884736, 2304,
    2304, 2304, 3538944, 9216, 3538944, 2304, 384, 384, 12288000, 32000};
static const int ALPHA_E[20] = {
    9216, 2304, 8192, 32000, 12288000, 2304, 2304, 2304, 2304, 384, 384,
    98304, 12288000, 3538944, 3538944, 884736, 884736, 2304, 884736, 884736};
static const int ALPHA_TO_SIG[20] = {
    13, 15, 0, 19, 18, 4, 3, 11, 10, 17, 16, 2, 1, 12, 14, 6, 8, 9, 5, 7};
static const int ALPHA_IDX_POS = 2;
static const int FSIZES[19] = {
    12288000, 98304, 2304, 2304, 884736, 884736, 884736, 884736, 2304,
    2304, 2304, 3538944, 9216, 3538944, 2304, 384, 384, 12288000, 32000};

static bool match_pat(const int* s, const int* E, int idx_pos,
                      int fmult, int idx_mult) {
    for (int i = 0; i < 20; i++) {
        long long expect = (long long)E[i] * ((i == idx_pos) ? idx_mult : fmult);
        if ((long long)s[i] != expect) return false;
    }
    return true;
}

extern "C" void kernel_launch(void* const* d_in, const int* in_sizes, int n_in,
                              void* d_out, int out_size) {
    if (n_in != 20) return;

    int in_mode = -2;
    bool alpha = false;
    if      (match_pat(in_sizes, SIG_E,   0,             1, 1)) { in_mode = -1; }
    else if (match_pat(in_sizes, ALPHA_E, ALPHA_IDX_POS, 1, 1)) { in_mode = -1; alpha = true; }
    else if (match_pat(in_sizes, SIG_E,   0,             4, 4)) { in_mode = 0; }
    else if (match_pat(in_sizes, ALPHA_E, ALPHA_IDX_POS, 4, 4)) { in_mode = 0; alpha = true; }
    else if (match_pat(in_sizes, SIG_E,   0,             2, 4)) { in_mode = 1; }
    else if (match_pat(in_sizes, ALPHA_E, ALPHA_IDX_POS, 2, 4)) { in_mode = 1; alpha = true; }
    if (in_mode == -2) return;

    const void* p[20];
    if (alpha) { for (int i = 0; i < 20; i++) p[ALPHA_TO_SIG[i]] = d_in[i]; }
    else       { for (int i = 0; i < 20; i++) p[i] = d_in[i]; }

    long long osz = (long long)out_size;
    const long long OE = (long long)M_TOK * V;
    int out_mode; int lm_rows;
    if      (osz == OE)     { out_mode = -1; lm_rows = M_TOK; }
    else if (osz == 4 * OE) { out_mode = 0;  lm_rows = M_TOK; }
    else if (osz == 2 * OE) { out_mode = 1;  lm_rows = M_TOK; }
    else                    { out_mode = 0;  lm_rows = 0;     }

    const int* idx = (const int*)p[0];

    flags_kernel<<<1, 256>>>(p[1], in_mode, out_mode);
    long long off[19];
    {
        long long o = 0;
        for (int i = 0; i < 19; i++) {
            off[i] = o;
            convert_kernel<<<(FSIZES[i] + 255) / 256, 256>>>(p[i + 1], o, FSIZES[i]);
            o += FSIZES[i];
        }
    }
    const long long oTok = off[0],  oPos = off[1];
    const long long oL1g = off[2],  oL1b = off[3];
    const long long oWq = off[4], oWk = off[5], oWv = off[6], oWo = off[7];
    const long long oWob = off[8], oL2g = off[9], oL2b = off[10];
    const long long oW1 = off[11], oB1 = off[12], oW2 = off[13], oB2 = off[14];
    const long long oLfg = off[15], oLfb = off[16], oLmw = off[17], oLmb = off[18];

    embed_kernel<<<M_TOK, C>>>(idx, oTok, oPos);

    dim3 gC (C  / 128, M_TOK / 128);
    dim3 gF (FF / 128, M_TOK / 128);
    dim3 gV (V  / 128, M_TOK / 128);

    // scratch selectors: 0=x 1=h 2=q 3=k 4=v 5=att 6=mlp
    for (int l = 0; l < NL; l++) {
        long long wq_l = oWq + (long long)l * C * C;
        long long wk_l = oWk + (long long)l * C * C;
        long long wv_l = oWv + (long long)l * C * C;
        long long wo_l = oWo + (long long)l * C * C;
        long long wob_l = oWob + (long long)l * C;
        long long w1_l = oW1 + (long long)l * C * FF;
        long long b1_l = oB1 + (long long)l * FF;
        long long w2_l = oW2 + (long long)l * FF * C;
        long long b2_l = oB2 + (long long)l * C;

        ln_kernel<<<M_TOK, 128>>>(0, oL1g + l * C, oL1b + l * C, 1);
        gemm_kernel<false,false,false,false><<<gC, 256>>>(1, wq_l, 0, 2, nullptr, M_TOK, C, C, M_TOK);
        gemm_kernel<false,false,false,false><<<gC, 256>>>(1, wk_l, 0, 3, nullptr, M_TOK, C, C, M_TOK);
        gemm_kernel<false,false,false,false><<<gC, 256>>>(1, wv_l, 0, 4, nullptr, M_TOK, C, C, M_TOK);
        attn_kernel<<<BB * HN, 256>>>();
        gemm_kernel<true,false,true,false><<<gC, 256>>>(5, wo_l, wob_l, 0, nullptr, M_TOK, C, C, M_TOK);
        ln_kernel<<<M_TOK, 128>>>(0, oL2g + l * C, oL2b + l * C, 1);
        // FIX: (M, N, K) = (M_TOK, FF, C) for W1
        gemm_kernel<true,true,false,false><<<gF, 256>>>(1, w1_l, b1_l, 6, nullptr, M_TOK, FF, C, M_TOK);
        // FIX: (M, N, K) = (M_TOK, C, FF) for W2
        gemm_kernel<true,false,true,false><<<gC, 256>>>(6, w2_l, b2_l, 0, nullptr, M_TOK, C, FF, M_TOK);
    }

    ln_kernel<<<M_TOK, 128>>>(0, oLfg, oLfb, 1);
    // FIX: (M, N, K) = (M_TOK, V, C) for LM head
    gemm_kernel<true,false,false,true><<<gV, 256>>>(1, oLmw, oLmb, 0, d_out, M_TOK, V, C, lm_rows);
}

// round 8
// speedup vs baseline: 5.7945x; 5.7945x over previous
#include <cuda_runtime.h>
#include <cuda_bf16.h>
#include <cstdint>

// ---------------------------------------------------------------------------
// BarbershopTransformer: 6-layer GPT forward, B=32 T=256 C=384 H=6 D=64 V=32000
// Round 8: tf32 mma.sync tensor-core GEMMs (128x128x32 tiles) + flash-style
// attention with smem K/V chunks. f32 everywhere else.
// ---------------------------------------------------------------------------

#define NL    6
#define C     384
#define HN    6
#define HD    64
#define TT    256
#define BB    32
#define M_TOK (BB*TT)          // 8192
#define FF    (4*C)            // 1536
#define V     32000

__device__ float g_x  [M_TOK*C];
__device__ float g_h  [M_TOK*C];
__device__ float g_q  [M_TOK*C];
__device__ float g_k  [M_TOK*C];
__device__ float g_v  [M_TOK*C];
__device__ float g_att[M_TOK*C];
__device__ float g_mlp[M_TOK*FF];

#define WBUF_TOTAL 35349248
__device__ float g_wbuf[WBUF_TOTAL];
__device__ int   g_in_bf16;
__device__ int   g_out_bf16;

__device__ __forceinline__ float* buf_sel(int s) {
    switch (s) {
        case 0: return g_x;
        case 1: return g_h;
        case 2: return g_q;
        case 3: return g_k;
        case 4: return g_v;
        case 5: return g_att;
        default: return g_mlp;   // 6
    }
}

// ---------------------------------------------------------------------------
__global__ void flags_kernel(const void* buf, int in_mode, int out_mode) {
    __shared__ int sh;
    int tid = threadIdx.x;
    if (tid == 0) sh = 0;
    __syncthreads();
    if (in_mode < 0) {
        const __nv_bfloat16* s = (const __nv_bfloat16*)buf;
        int cnt = 0;
        for (int i = tid; i < 4096; i += 256) {
            float f = __bfloat162float(s[i]);
            if (!isfinite(f) || fabsf(f) > 8.0f) cnt++;
        }
        atomicAdd(&sh, cnt);
    }
    __syncthreads();
    if (tid == 0) {
        int in_bf16 = (in_mode < 0) ? ((sh > 64) ? 0 : 1) : in_mode;
        g_in_bf16  = in_bf16;
        g_out_bf16 = (out_mode < 0) ? in_bf16 : out_mode;
    }
}

__global__ void convert_kernel(const void* src, long long off, int n) {
    int i = blockIdx.x * blockDim.x + threadIdx.x;
    if (i >= n) return;
    float vv;
    if (g_in_bf16) vv = __bfloat162float(((const __nv_bfloat16*)src)[i]);
    else           vv = ((const float*)src)[i];
    long long o = off + i;
    if (o >= 0 && o < WBUF_TOTAL) g_wbuf[o] = vv;
}

// ---------------------------------------------------------------------------
__global__ void embed_kernel(const int* __restrict__ idx,
                             long long tokOff, long long posOff) {
    int m = blockIdx.x;
    int c = threadIdx.x;
    int t = m & (TT - 1);
    int tk = idx[m];
    if ((unsigned)tk >= (unsigned)V) tk = 0;
    const float* tok = g_wbuf + tokOff;
    const float* pos = g_wbuf + posOff;
    g_x[m * C + c] = tok[tk * C + c] + pos[t * C + c];
}

// ---------------------------------------------------------------------------
__global__ void ln_kernel(int inSel, long long gOff, long long bOff, int outSel) {
    __shared__ float red[4];
    __shared__ float stat[2];
    const float* x = buf_sel(inSel);
    float* out     = buf_sel(outSel);
    const float* g = g_wbuf + gOff;
    const float* b = g_wbuf + bOff;
    int row = blockIdx.x, tid = threadIdx.x;
    const float* xr = x + (size_t)row * C;
    float v0 = xr[tid], v1 = xr[tid + 128], v2 = xr[tid + 256];
    float s = v0 + v1 + v2;
    #pragma unroll
    for (int o = 16; o; o >>= 1) s += __shfl_xor_sync(0xffffffffu, s, o);
    if ((tid & 31) == 0) red[tid >> 5] = s;
    __syncthreads();
    if (tid == 0) stat[0] = (red[0] + red[1] + red[2] + red[3]) * (1.0f / C);
    __syncthreads();
    float m = stat[0];
    float d0 = v0 - m, d1 = v1 - m, d2 = v2 - m;
    float q = d0 * d0 + d1 * d1 + d2 * d2;
    #pragma unroll
    for (int o = 16; o; o >>= 1) q += __shfl_xor_sync(0xffffffffu, q, o);
    if ((tid & 31) == 0) red[tid >> 5] = q;
    __syncthreads();
    if (tid == 0)
        stat[1] = rsqrtf((red[0] + red[1] + red[2] + red[3]) * (1.0f / C) + 1e-5f);
    __syncthreads();
    float r = stat[1];
    float* o = out + (size_t)row * C;
    o[tid]       = d0 * r * g[tid]       + b[tid];
    o[tid + 128] = d1 * r * g[tid + 128] + b[tid + 128];
    o[tid + 256] = d2 * r * g[tid + 256] + b[tid + 256];
}

// ---------------------------------------------------------------------------
// tf32 helpers
__device__ __forceinline__ float tf32r(float x) {
    float y;
    asm("cvt.rna.tf32.f32 %0, %1;" : "=f"(y) : "f"(x));
    return y;
}
__device__ __forceinline__ void mma_tf32(float& c0, float& c1, float& c2, float& c3,
                                         uint32_t a0, uint32_t a1, uint32_t a2, uint32_t a3,
                                         uint32_t b0, uint32_t b1) {
    asm volatile(
        "mma.sync.aligned.m16n8k8.row.col.f32.tf32.tf32.f32 "
        "{%0,%1,%2,%3}, {%4,%5,%6,%7}, {%8,%9}, {%0,%1,%2,%3};\n"
        : "+f"(c0), "+f"(c1), "+f"(c2), "+f"(c3)
        : "r"(a0), "r"(a1), "r"(a2), "r"(a3), "r"(b0), "r"(b1));
}

// ---------------------------------------------------------------------------
// tf32 MMA GEMM: C[M,N] = A[M,K] @ B[K,N] (+bias,+relu,+residual from g_x).
// BM=BN=128, BK=32, 256 thr (8 warps, each 64x32). K%32==0, M,N %128==0.
#define ASTR 36
#define BSTR 132
template<bool BIAS, bool RELU, bool RES, bool DYNOUT>
__global__ void __launch_bounds__(256, 2)
mma_gemm(int aSel, long long bOff, long long biasOff,
         int outSel, void* dOutPtr, int M, int N, int K, int Mlim) {
    __shared__ float As[128 * ASTR];
    __shared__ float Bs[32 * BSTR];
    const float* A  = buf_sel(aSel);
    const float* B  = g_wbuf + bOff;
    const float* bi = g_wbuf + biasOff;

    int tid = threadIdx.x;
    int warp = tid >> 5, lane = tid & 31;
    int wm = warp >> 2;          // 0..1  (64-row slabs)
    int wn = warp & 3;           // 0..3  (32-col slabs)
    int g = lane >> 2, t = lane & 3;
    int bm = blockIdx.y * 128, bn = blockIdx.x * 128;

    float acc[4][4][4];
    #pragma unroll
    for (int mi = 0; mi < 4; mi++)
        #pragma unroll
        for (int ni = 0; ni < 4; ni++)
            #pragma unroll
            for (int cc = 0; cc < 4; cc++) acc[mi][ni][cc] = 0.f;

    const uint32_t* Asu = (const uint32_t*)As;
    const uint32_t* Bsu = (const uint32_t*)Bs;

    for (int k0 = 0; k0 < K; k0 += 32) {
        // stage A tile: 128 rows x 32 k  (1024 float4)
        #pragma unroll
        for (int u = 0; u < 4; u++) {
            int f = tid + u * 256;
            int r = f >> 3, kc = (f & 7) * 4;
            float4 va = *(const float4*)(A + (size_t)(bm + r) * K + k0 + kc);
            va.x = tf32r(va.x); va.y = tf32r(va.y);
            va.z = tf32r(va.z); va.w = tf32r(va.w);
            *(float4*)(As + r * ASTR + kc) = va;
        }
        // stage B tile: 32 rows(k) x 128 cols(n)
        #pragma unroll
        for (int u = 0; u < 4; u++) {
            int f = tid + u * 256;
            int r = f >> 5, nc = (f & 31) * 4;
            float4 vb = *(const float4*)(B + (size_t)(k0 + r) * N + bn + nc);
            vb.x = tf32r(vb.x); vb.y = tf32r(vb.y);
            vb.z = tf32r(vb.z); vb.w = tf32r(vb.w);
            *(float4*)(Bs + r * BSTR + nc) = vb;
        }
        __syncthreads();
        #pragma unroll
        for (int kk = 0; kk < 32; kk += 8) {
            uint32_t af[4][4];
            #pragma unroll
            for (int mi = 0; mi < 4; mi++) {
                int row = wm * 64 + mi * 16;
                af[mi][0] = Asu[(row + g)     * ASTR + kk + t];
                af[mi][1] = Asu[(row + g + 8) * ASTR + kk + t];
                af[mi][2] = Asu[(row + g)     * ASTR + kk + t + 4];
                af[mi][3] = Asu[(row + g + 8) * ASTR + kk + t + 4];
            }
            uint32_t bf[4][2];
            #pragma unroll
            for (int ni = 0; ni < 4; ni++) {
                int col = wn * 32 + ni * 8 + g;
                bf[ni][0] = Bsu[(kk + t)     * BSTR + col];
                bf[ni][1] = Bsu[(kk + t + 4) * BSTR + col];
            }
            #pragma unroll
            for (int mi = 0; mi < 4; mi++)
                #pragma unroll
                for (int ni = 0; ni < 4; ni++)
                    mma_tf32(acc[mi][ni][0], acc[mi][ni][1],
                             acc[mi][ni][2], acc[mi][ni][3],
                             af[mi][0], af[mi][1], af[mi][2], af[mi][3],
                             bf[ni][0], bf[ni][1]);
        }
        __syncthreads();
    }

    // epilogue
    bool store_bf16 = DYNOUT ? (g_out_bf16 != 0) : false;
    float* outBuf = DYNOUT ? nullptr : buf_sel(outSel);
    #pragma unroll
    for (int mi = 0; mi < 4; mi++) {
        #pragma unroll
        for (int ni = 0; ni < 4; ni++) {
            int col = bn + wn * 32 + ni * 8 + t * 2;
            float b0 = 0.f, b1 = 0.f;
            if (BIAS) { b0 = bi[col]; b1 = bi[col + 1]; }
            #pragma unroll
            for (int half = 0; half < 2; half++) {
                int row = bm + wm * 64 + mi * 16 + g + half * 8;
                if (row >= Mlim) continue;
                float v0 = acc[mi][ni][half * 2 + 0];
                float v1 = acc[mi][ni][half * 2 + 1];
                if (BIAS) { v0 += b0; v1 += b1; }
                if (RELU) { v0 = fmaxf(v0, 0.f); v1 = fmaxf(v1, 0.f); }
                long long base = (long long)row * N + col;
                if (RES) {
                    float2 rr = *(const float2*)(g_x + base);
                    v0 += rr.x; v1 += rr.y;
                }
                if (DYNOUT) {
                    if (store_bf16) {
                        __nv_bfloat162 pk = __floats2bfloat162_rn(v0, v1);
                        *(__nv_bfloat162*)((__nv_bfloat16*)dOutPtr + base) = pk;
                    } else {
                        *(float2*)((float*)dOutPtr + base) = make_float2(v0, v1);
                    }
                } else {
                    *(float2*)(outBuf + base) = make_float2(v0, v1);
                }
            }
        }
    }
}

// ---------------------------------------------------------------------------
// Flash attention: block = (b,h,qtile of 32), 8 warps x 4 queries.
// K/V chunks of 64 staged in static smem; online softmax; q in registers.
#define KSTR 65
__global__ void __launch_bounds__(256)
flash_attn() {
    __shared__ float Ks[64 * KSTR];     // 16640 B
    __shared__ float Vs[64 * 64];       // 16384 B
    __shared__ float Ps[8][4][64];      //  8192 B
    int blk = blockIdx.x;
    int qt = blk & 7;
    int bh = blk >> 3;
    int b = bh / HN, h = bh % HN;
    int tid = threadIdx.x, w = tid >> 5, lane = tid & 31;
    int qbase = qt * 32 + w * 4;
    const float scale = rsqrtf((float)C);

    float q[4][2];
    #pragma unroll
    for (int qi = 0; qi < 4; qi++) {
        long long base = (long long)(b * TT + qbase + qi) * C + h * HD;
        q[qi][0] = g_q[base + lane]      * scale;
        q[qi][1] = g_q[base + lane + 32] * scale;
    }
    float o[4][2];
    float m[4], l[4];
    #pragma unroll
    for (int qi = 0; qi < 4; qi++) {
        o[qi][0] = o[qi][1] = 0.f;
        m[qi] = -1e30f; l[qi] = 0.f;
    }

    int nch = (qt * 32 + 31) / 64 + 1;
    for (int c = 0; c < nch; c++) {
        __syncthreads();
        // stage K (padded stride) and V chunk
        #pragma unroll
        for (int u = 0; u < 4; u++) {
            int f = tid + u * 256;
            int r = f >> 4, dc = (f & 15) * 4;
            long long gb = (long long)(b * TT + c * 64 + r) * C + h * HD + dc;
            float4 kv = *(const float4*)(g_k + gb);
            Ks[r * KSTR + dc]     = kv.x;
            Ks[r * KSTR + dc + 1] = kv.y;
            Ks[r * KSTR + dc + 2] = kv.z;
            Ks[r * KSTR + dc + 3] = kv.w;
            float4 vv = *(const float4*)(g_v + gb);
            *(float4*)(Vs + r * 64 + dc) = vv;
        }
        __syncthreads();

        // scores: 2 s per lane (lane, lane+32)
        float sc[4][2];
        #pragma unroll
        for (int qi = 0; qi < 4; qi++) { sc[qi][0] = 0.f; sc[qi][1] = 0.f; }
        #pragma unroll 8
        for (int d = 0; d < 32; d++) {
            float k0 = Ks[lane * KSTR + d];
            float k1 = Ks[(lane + 32) * KSTR + d];
            #pragma unroll
            for (int qi = 0; qi < 4; qi++) {
                float qd = __shfl_sync(0xffffffffu, q[qi][0], d);
                sc[qi][0] = fmaf(qd, k0, sc[qi][0]);
                sc[qi][1] = fmaf(qd, k1, sc[qi][1]);
            }
        }
        #pragma unroll 8
        for (int d = 0; d < 32; d++) {
            float k0 = Ks[lane * KSTR + 32 + d];
            float k1 = Ks[(lane + 32) * KSTR + 32 + d];
            #pragma unroll
            for (int qi = 0; qi < 4; qi++) {
                float qd = __shfl_sync(0xffffffffu, q[qi][1], d);
                sc[qi][0] = fmaf(qd, k0, sc[qi][0]);
                sc[qi][1] = fmaf(qd, k1, sc[qi][1]);
            }
        }

        int s0 = c * 64 + lane, s1 = s0 + 32;
        #pragma unroll
        for (int qi = 0; qi < 4; qi++) {
            int tq = qbase + qi;
            float a0 = (s0 <= tq) ? sc[qi][0] : -1e30f;
            float a1 = (s1 <= tq) ? sc[qi][1] : -1e30f;
            float cm = fmaxf(a0, a1);
            #pragma unroll
            for (int off = 16; off; off >>= 1)
                cm = fmaxf(cm, __shfl_xor_sync(0xffffffffu, cm, off));
            float nm = fmaxf(m[qi], cm);
            float fac = __expf(m[qi] - nm);
            float p0 = __expf(a0 - nm);
            float p1 = __expf(a1 - nm);
            float ps = p0 + p1;
            #pragma unroll
            for (int off = 16; off; off >>= 1)
                ps += __shfl_xor_sync(0xffffffffu, ps, off);
            m[qi] = nm;
            l[qi] = l[qi] * fac + ps;
            o[qi][0] *= fac; o[qi][1] *= fac;
            Ps[w][qi][lane]      = p0;
            Ps[w][qi][lane + 32] = p1;
        }
        __syncwarp();
        // AV accumulate
        #pragma unroll 4
        for (int s = 0; s < 64; s++) {
            float v0 = Vs[s * 64 + lane];
            float v1 = Vs[s * 64 + lane + 32];
            #pragma unroll
            for (int qi = 0; qi < 4; qi++) {
                float pv = Ps[w][qi][s];
                o[qi][0] = fmaf(pv, v0, o[qi][0]);
                o[qi][1] = fmaf(pv, v1, o[qi][1]);
            }
        }
    }

    #pragma unroll
    for (int qi = 0; qi < 4; qi++) {
        float inv = 1.f / l[qi];
        long long base = (long long)(b * TT + qbase + qi) * C + h * HD;
        g_att[base + lane]      = o[qi][0] * inv;
        g_att[base + lane + 32] = o[qi][1] * inv;
    }
}

// ---------------------------------------------------------------------------
static const int SIG_E[20] = {
    8192, 12288000, 98304, 2304, 2304, 884736, 884736, 884736, 884736, 2304,
    2304, 2304, 3538944, 9216, 3538944, 2304, 384, 384, 12288000, 32000};
static const int ALPHA_E[20] = {
    9216, 2304, 8192, 32000, 12288000, 2304, 2304, 2304, 2304, 384, 384,
    98304, 12288000, 3538944, 3538944, 884736, 884736, 2304, 884736, 884736};
static const int ALPHA_TO_SIG[20] = {
    13, 15, 0, 19, 18, 4, 3, 11, 10, 17, 16, 2, 1, 12, 14, 6, 8, 9, 5, 7};
static const int ALPHA_IDX_POS = 2;
static const int FSIZES[19] = {
    12288000, 98304, 2304, 2304, 884736, 884736, 884736, 884736, 2304,
    2304, 2304, 3538944, 9216, 3538944, 2304, 384, 384, 12288000, 32000};

static bool match_pat(const int* s, const int* E, int idx_pos,
                      int fmult, int idx_mult) {
    for (int i = 0; i < 20; i++) {
        long long expect = (long long)E[i] * ((i == idx_pos) ? idx_mult : fmult);
        if ((long long)s[i] != expect) return false;
    }
    return true;
}

extern "C" void kernel_launch(void* const* d_in, const int* in_sizes, int n_in,
                              void* d_out, int out_size) {
    if (n_in != 20) return;

    int in_mode = -2;
    bool alpha = false;
    if      (match_pat(in_sizes, SIG_E,   0,             1, 1)) { in_mode = -1; }
    else if (match_pat(in_sizes, ALPHA_E, ALPHA_IDX_POS, 1, 1)) { in_mode = -1; alpha = true; }
    else if (match_pat(in_sizes, SIG_E,   0,             4, 4)) { in_mode = 0; }
    else if (match_pat(in_sizes, ALPHA_E, ALPHA_IDX_POS, 4, 4)) { in_mode = 0; alpha = true; }
    else if (match_pat(in_sizes, SIG_E,   0,             2, 4)) { in_mode = 1; }
    else if (match_pat(in_sizes, ALPHA_E, ALPHA_IDX_POS, 2, 4)) { in_mode = 1; alpha = true; }
    if (in_mode == -2) return;

    const void* p[20];
    if (alpha) { for (int i = 0; i < 20; i++) p[ALPHA_TO_SIG[i]] = d_in[i]; }
    else       { for (int i = 0; i < 20; i++) p[i] = d_in[i]; }

    long long osz = (long long)out_size;
    const long long OE = (long long)M_TOK * V;
    int out_mode; int lm_rows;
    if      (osz == OE)     { out_mode = -1; lm_rows = M_TOK; }
    else if (osz == 4 * OE) { out_mode = 0;  lm_rows = M_TOK; }
    else if (osz == 2 * OE) { out_mode = 1;  lm_rows = M_TOK; }
    else                    { out_mode = 0;  lm_rows = 0;     }

    const int* idx = (const int*)p[0];

    flags_kernel<<<1, 256>>>(p[1], in_mode, out_mode);
    long long off[19];
    {
        long long o = 0;
        for (int i = 0; i < 19; i++) {
            off[i] = o;
            convert_kernel<<<(FSIZES[i] + 255) / 256, 256>>>(p[i + 1], o, FSIZES[i]);
            o += FSIZES[i];
        }
    }
    const long long oTok = off[0],  oPos = off[1];
    const long long oL1g = off[2],  oL1b = off[3];
    const long long oWq = off[4], oWk = off[5], oWv = off[6], oWo = off[7];
    const long long oWob = off[8], oL2g = off[9], oL2b = off[10];
    const long long oW1 = off[11], oB1 = off[12], oW2 = off[13], oB2 = off[14];
    const long long oLfg = off[15], oLfb = off[16], oLmw = off[17], oLmb = off[18];

    embed_kernel<<<M_TOK, C>>>(idx, oTok, oPos);

    dim3 gC (C  / 128, M_TOK / 128);
    dim3 gF (FF / 128, M_TOK / 128);
    dim3 gV (V  / 128, M_TOK / 128);

    // scratch selectors: 0=x 1=h 2=q 3=k 4=v 5=att 6=mlp
    for (int l = 0; l < NL; l++) {
        long long wq_l = oWq + (long long)l * C * C;
        long long wk_l = oWk + (long long)l * C * C;
        long long wv_l = oWv + (long long)l * C * C;
        long long wo_l = oWo + (long long)l * C * C;
        long long wob_l = oWob + (long long)l * C;
        long long w1_l = oW1 + (long long)l * C * FF;
        long long b1_l = oB1 + (long long)l * FF;
        long long w2_l = oW2 + (long long)l * FF * C;
        long long b2_l = oB2 + (long long)l * C;

        ln_kernel<<<M_TOK, 128>>>(0, oL1g + l * C, oL1b + l * C, 1);
        mma_gemm<false,false,false,false><<<gC, 256>>>(1, wq_l, 0, 2, nullptr, M_TOK, C, C, M_TOK);
        mma_gemm<false,false,false,false><<<gC, 256>>>(1, wk_l, 0, 3, nullptr, M_TOK, C, C, M_TOK);
        mma_gemm<false,false,false,false><<<gC, 256>>>(1, wv_l, 0, 4, nullptr, M_TOK, C, C, M_TOK);
        flash_attn<<<BB * HN * 8, 256>>>();
        mma_gemm<true,false,true,false><<<gC, 256>>>(5, wo_l, wob_l, 0, nullptr, M_TOK, C, C, M_TOK);
        ln_kernel<<<M_TOK, 128>>>(0, oL2g + l * C, oL2b + l * C, 1);
        mma_gemm<true,true,false,false><<<gF, 256>>>(1, w1_l, b1_l, 6, nullptr, M_TOK, FF, C, M_TOK);
        mma_gemm<true,false,true,false><<<gC, 256>>>(6, w2_l, b2_l, 0, nullptr, M_TOK, C, FF, M_TOK);
    }

    ln_kernel<<<M_TOK, 128>>>(0, oLfg, oLfb, 1);
    mma_gemm<true,false,false,true><<<gV, 256>>>(1, oLmw, oLmb, 0, d_out, M_TOK, V, C, lm_rows);
}